// round 11
// baseline (speedup 1.0000x reference)
#include <cuda_runtime.h>
#include <cuda_bf16.h>
#include <cstdint>

#define EPS_LDM 1e-6f

static const int NSEL  = 16384;
static const int DIM   = 128;
static const int NEDGE = 500000;
static const int NTILE = 128;                      // 16384/128
static const int NTRI  = NTILE * (NTILE + 1) / 2;  // 8256 tiles
static const int NTC   = 296;                      // persistent CTAs = 148 SMs x 2 (one wave)
static const int NWTOT = NTC * 8;                  // total warps for link work

// Stage = one 64-col K-phase of a 128x128 tile: A-half + B-half in smem.
static const int KSTR2  = 72;             // bf16 per smem row: 64 data + 8 pad
static const int ROWB2  = KSTR2 * 2;      // 144 B rows (conflict-free for ldmatrix)
static const int HALFB  = 128 * ROWB2;    // 18432 B per matrix half
static const int STAGEB = 2 * HALFB;      // 36864 B per stage (A+B)
static const int DSMEM  = 2 * STAGEB + 256;

// Scratch (device globals; no allocation allowed)
__device__ double g_acc[2];                    // [0]=link, [1]=nonlink
__device__ unsigned g_done;
__device__ __nv_bfloat16 g_psb[NSEL * DIM];    // bf16 p_star[nodes_p_star] (rows n)
__device__ __nv_bfloat16 g_ppb[NSEL * DIM];    // bf16 p[nodes_p]           (cols m)
__device__ float g_sn[NSEL], g_sm[NSEL], g_bps[NSEL], g_bp[NSEL];

// ---------------- gather (+ accumulator reset) ----------------
__global__ void gather_kernel(const int* __restrict__ nodes_p_star,
                              const int* __restrict__ nodes_p,
                              const float* __restrict__ beta_p,
                              const float* __restrict__ beta_p_star,
                              const float* __restrict__ p,
                              const float* __restrict__ p_star) {
    if (blockIdx.x == 0 && threadIdx.x < 3) {
        if (threadIdx.x < 2) g_acc[threadIdx.x] = 0.0;
        else g_done = 0u;
    }
    int w    = (blockIdx.x * blockDim.x + threadIdx.x) >> 5;
    int lane = threadIdx.x & 31;
    if (w >= 2 * NSEL) return;
    bool is_s = (w < NSEL);
    int row   = is_s ? w : (w - NSEL);
    int node  = is_s ? nodes_p_star[row] : nodes_p[row];
    const float4* src = reinterpret_cast<const float4*>((is_s ? p_star : p) + (size_t)node * DIM);
    float4 v = src[lane];

    __nv_bfloat162 h0 = __floats2bfloat162_rn(v.x, v.y);
    __nv_bfloat162 h1 = __floats2bfloat162_rn(v.z, v.w);
    uint2 packed;
    packed.x = *reinterpret_cast<unsigned*>(&h0);
    packed.y = *reinterpret_cast<unsigned*>(&h1);
    __nv_bfloat16* dstb = (is_s ? g_psb : g_ppb) + (size_t)row * DIM;
    reinterpret_cast<uint2*>(dstb)[lane] = packed;

    float s = v.x * v.x + v.y * v.y + v.z * v.z + v.w * v.w;
    #pragma unroll
    for (int o = 16; o > 0; o >>= 1) s += __shfl_xor_sync(0xffffffffu, s, o);
    if (lane == 0) {
        if (is_s) { g_sn[row] = s; g_bps[row] = beta_p_star[node]; }
        else      { g_sm[row] = s; g_bp[row]  = beta_p[node]; }
    }
}

// ---------------- helpers ----------------
__device__ __forceinline__ uint32_t cvta_s(const void* ptr) {
    return (uint32_t)__cvta_generic_to_shared(ptr);
}
__device__ __forceinline__ void cp16(uint32_t s, const void* g) {
    asm volatile("cp.async.cg.shared.global [%0], [%1], 16;" :: "r"(s), "l"(g));
}
#define CP_COMMIT() asm volatile("cp.async.commit_group;")
#define CP_WAIT1()  asm volatile("cp.async.wait_group 1;")
#define CP_WAIT0()  asm volatile("cp.async.wait_group 0;")
__device__ __forceinline__ void ldsm_x4(uint32_t* r, uint32_t addr) {
    asm volatile("ldmatrix.sync.aligned.m8n8.x4.shared.b16 {%0,%1,%2,%3}, [%4];"
                 : "=r"(r[0]), "=r"(r[1]), "=r"(r[2]), "=r"(r[3]) : "r"(addr));
}
__device__ __forceinline__ void mma_bf16(float* c, const uint32_t* a, const uint32_t* b) {
    asm volatile("mma.sync.aligned.m16n8k16.row.col.f32.bf16.bf16.f32 "
                 "{%0,%1,%2,%3}, {%4,%5,%6,%7}, {%8,%9}, {%0,%1,%2,%3};"
                 : "+f"(c[0]), "+f"(c[1]), "+f"(c[2]), "+f"(c[3])
                 : "r"(a[0]), "r"(a[1]), "r"(a[2]), "r"(a[3]), "r"(b[0]), "r"(b[1]));
}
__device__ __forceinline__ float fast_sqrt(float x) {
    float r; asm("sqrt.approx.f32 %0, %1;" : "=f"(r) : "f"(x)); return r;
}
__device__ __forceinline__ float fast_ex2(float x) {
    float r; asm("ex2.approx.f32 %0, %1;" : "=f"(r) : "f"(x)); return r;
}

__device__ __forceinline__ void tile_ij(int t, int& bi, int& bj) {
    float T = 2.f * NTILE + 1.f;
    int i = (int)((T - sqrtf(T * T - 8.f * (float)t)) * 0.5f);
    if (i < 0) i = 0;
    while (i > 0 && i * NTILE - (i * (i - 1)) / 2 > t) i--;
    while ((i + 1) * NTILE - ((i + 1) * i) / 2 <= t) i++;
    bi = i;
    bj = i + (t - (i * NTILE - (i * (i - 1)) / 2));
}

// ---------------- fused persistent pipelined kernel ----------------
__global__ void __launch_bounds__(256, 2) fused_kernel(
        const int* __restrict__ edges,
        const float* __restrict__ beta_p,
        const float* __restrict__ beta_p_star,
        const float* __restrict__ p,
        const float* __restrict__ p_star,
        float* __restrict__ out) {
    extern __shared__ __align__(16) char dynraw[];
    __shared__ float ssn[2][128], sbn[2][128], ssm[2][128], sbm[2][128];
    __shared__ float red[8], redl[8];

    const float LOG2E = 1.4426950408889634f;
    int bid = blockIdx.x, tid = threadIdx.x, wid = tid >> 5, lane = tid & 31;
    int wr = wid & 3;    // warp row group: 32 rows
    int wc = wid >> 2;   // warp col group: 64 cols

    uint32_t smbase = (cvta_s(dynraw) + 127u) & ~127u;

    // number of tiles this CTA owns; total stages = 2 * ntiles
    int ntiles = (NTRI - bid + NTC - 1) / NTC;
    int nstages = 2 * ntiles;

    auto stage_tile = [&](int s, int& bi, int& bj, int& ph) {
        ph = s & 1;
        tile_ij(bid + (s >> 1) * NTC, bi, bj);
    };
    auto prefetch_stage = [&](int s) {
        int bi, bj, ph;
        stage_tile(s, bi, bj, ph);
        int n0 = bi << 7, m0 = bj << 7, koff = ph * 64;
        uint32_t buf = smbase + (uint32_t)(s & 1) * STAGEB;
        #pragma unroll
        for (int it = 0; it < 4; it++) {
            int idx = tid + it * 256;       // 0..1023
            int row = idx >> 3, c = idx & 7;
            uint32_t so = (uint32_t)(row * ROWB2 + c * 16);
            cp16(buf + so,         g_psb + (size_t)(n0 + row) * DIM + koff + c * 8);
            cp16(buf + HALFB + so, g_ppb + (size_t)(m0 + row) * DIM + koff + c * 8);
        }
        if (ph == 0) {   // stage norms/betas for this tile into normbuf[(s>>1)&1]
            int b = (s >> 1) & 1;
            if (tid < 128) { ssn[b][tid] = g_sn[n0 + tid]; sbn[b][tid] = g_bps[n0 + tid] * LOG2E; }
            else { int q = tid - 128; ssm[b][q] = g_sm[m0 + q]; sbm[b][q] = g_bp[m0 + q] * LOG2E; }
        }
        CP_COMMIT();
    };

    int ecur = bid * 8 + wid;     // this warp's edge cursor (grid-stride by NWTOT)
    float lsum = 0.f;
    auto link_batch2 = [&]() {
        #pragma unroll
        for (int k = 0; k < 2; k++) {
            int ei = ecur + k * NWTOT;
            if (ei < NEDGE) {
                int e0 = edges[ei];
                int e1 = edges[NEDGE + ei];
                float4 a = reinterpret_cast<const float4*>(p      + (size_t)e0 * DIM)[lane];
                float4 b = reinterpret_cast<const float4*>(p_star + (size_t)e1 * DIM)[lane];
                float dx = a.x - b.x + EPS_LDM;
                float dy = a.y - b.y + EPS_LDM;
                float dz = a.z - b.z + EPS_LDM;
                float dw = a.w - b.w + EPS_LDM;
                float s = dx * dx + dy * dy + dz * dz + dw * dw;
                #pragma unroll
                for (int o = 16; o > 0; o >>= 1) s += __shfl_xor_sync(0xffffffffu, s, o);
                if (lane == 0) lsum += beta_p_star[e0] + beta_p[e1] - sqrtf(s);
            }
        }
        ecur += 2 * NWTOT;
    };

    float acc[2][8][4];
    float part = 0.f;

    // prologue
    prefetch_stage(0);

    for (int s = 0; s < nstages; s++) {
        bool havenext = (s + 1) < nstages;
        if (havenext) prefetch_stage(s + 1);
        link_batch2();                       // LDG latency overlaps cp.async fill
        if (havenext) { CP_WAIT1(); } else { CP_WAIT0(); }
        __syncthreads();

        int ph = s & 1;
        if (ph == 0) {
            #pragma unroll
            for (int g = 0; g < 2; g++)
                #pragma unroll
                for (int j = 0; j < 8; j++)
                    #pragma unroll
                    for (int q = 0; q < 4; q++) acc[g][j][q] = 0.f;
        }

        // ---- MMA on stage buffer (4 K-steps of 16) ----
        uint32_t bufA = smbase + (uint32_t)(s & 1) * STAGEB;
        uint32_t bufB = bufA + HALFB;
        #pragma unroll
        for (int ks = 0; ks < 4; ks++) {
            int kb = (ks * 16 + ((lane >> 4) << 3)) * 2;
            uint32_t a[2][4];
            #pragma unroll
            for (int g = 0; g < 2; g++) {
                int row = wr * 32 + g * 16 + (lane & 15);
                ldsm_x4(a[g], bufA + row * ROWB2 + kb);
            }
            uint32_t b[8][2];
            #pragma unroll
            for (int h = 0; h < 4; h++) {
                int row = wc * 64 + h * 16 + (lane & 15);
                uint32_t r[4];
                ldsm_x4(r, bufB + row * ROWB2 + kb);
                b[2 * h + 0][0] = r[0]; b[2 * h + 0][1] = r[2];
                b[2 * h + 1][0] = r[1]; b[2 * h + 1][1] = r[3];
            }
            #pragma unroll
            for (int g = 0; g < 2; g++)
                #pragma unroll
                for (int j = 0; j < 8; j++)
                    mma_bf16(acc[g][j], a[g], b[j]);
        }

        if (ph == 1) {
            // ---- epilogue for this tile ----
            link_batch2();   // LDG latency hides under the MUFU chain below
            int nb = (s >> 1) & 1;
            int bi, bj, php;
            stage_tile(s, bi, bj, php);
            int n0 = bi << 7, m0 = bj << 7;
            float s4[4] = {0.f, 0.f, 0.f, 0.f};
            if (bi != bj) {
                #pragma unroll
                for (int g = 0; g < 2; g++)
                    #pragma unroll
                    for (int h = 0; h < 2; h++) {
                        int row = wr * 32 + g * 16 + (lane >> 2) + h * 8;
                        float rs = ssn[nb][row], rb = sbn[nb][row];
                        #pragma unroll
                        for (int j = 0; j < 8; j++)
                            #pragma unroll
                            for (int c = 0; c < 2; c++) {
                                int col = wc * 64 + j * 8 + (lane & 3) * 2 + c;
                                float sq = fmaf(-2.f, acc[g][j][h * 2 + c], rs + ssm[nb][col]);
                                float d  = fast_sqrt(sq);
                                s4[h * 2 + c] += fast_ex2(fmaf(d, -LOG2E, rb + sbm[nb][col]));
                            }
                    }
            } else {
                #pragma unroll
                for (int g = 0; g < 2; g++)
                    #pragma unroll
                    for (int h = 0; h < 2; h++) {
                        int row = wr * 32 + g * 16 + (lane >> 2) + h * 8;
                        float rs = ssn[nb][row], rb = sbn[nb][row];
                        #pragma unroll
                        for (int j = 0; j < 8; j++)
                            #pragma unroll
                            for (int c = 0; c < 2; c++) {
                                int col = wc * 64 + j * 8 + (lane & 3) * 2 + c;
                                if (m0 + col > n0 + row) {
                                    float sq = fmaf(-2.f, acc[g][j][h * 2 + c], rs + ssm[nb][col]);
                                    float d  = fast_sqrt(sq);
                                    s4[h * 2 + c] += fast_ex2(fmaf(d, -LOG2E, rb + sbm[nb][col]));
                                }
                            }
                    }
            }
            part += (s4[0] + s4[1]) + (s4[2] + s4[3]);
        }
        __syncthreads();   // stage buffer (s&1) free for the prefetch at s+1's top
    }

    // drain any leftover link edges
    while (ecur < NEDGE) link_batch2();

    // --- reductions + finalize ---
    #pragma unroll
    for (int o = 16; o > 0; o >>= 1) part += __shfl_xor_sync(0xffffffffu, part, o);
    if (lane == 0) { red[wid] = part; redl[wid] = lsum; }
    __syncthreads();
    if (tid == 0) {
        float bs = 0.f, bl = 0.f;
        #pragma unroll
        for (int i = 0; i < 8; i++) { bs += red[i]; bl += redl[i]; }
        atomicAdd(&g_acc[1], (double)bs);
        atomicAdd(&g_acc[0], (double)bl);
        __threadfence();
        unsigned v = atomicAdd(&g_done, 1u);
        if (v == NTC - 1) {
            __threadfence();
            double link = *(volatile double*)&g_acc[0];
            double nonl = *(volatile double*)&g_acc[1];
            out[0] = (float)(nonl - link);
        }
    }
}

extern "C" void kernel_launch(void* const* d_in, const int* in_sizes, int n_in,
                              void* d_out, int out_size) {
    const int*   edges        = (const int*)d_in[0];
    const int*   nodes_p_star = (const int*)d_in[1];
    const int*   nodes_p      = (const int*)d_in[2];
    const float* beta_p       = (const float*)d_in[3];
    const float* beta_p_star  = (const float*)d_in[4];
    const float* p            = (const float*)d_in[5];
    const float* p_star       = (const float*)d_in[6];
    float*       out          = (float*)d_out;

    cudaFuncSetAttribute(fused_kernel, cudaFuncAttributeMaxDynamicSharedMemorySize, DSMEM);

    gather_kernel<<<(2 * NSEL + 7) / 8, 256>>>(nodes_p_star, nodes_p,
                                               beta_p, beta_p_star, p, p_star);

    fused_kernel<<<NTC, 256, DSMEM>>>(edges, beta_p, beta_p_star, p, p_star, out);
}